// round 9
// baseline (speedup 1.0000x reference)
#include <cuda_runtime.h>
#include <cuda_fp16.h>
#include <math.h>

#define N_NODES 100000
#define N_EDGES 3200000
#define NBLK_N 391

typedef unsigned long long u64;

// ---------------- static device scratch (allocation-free) ----------------
static __device__ float g_h0[400000];      // fp32, stride 4 (L1 gather; fp16 would overflow)
static __device__ float g_x1[800000];
static __device__ float g_x2[1600000];
static __device__ float g_x3[3200000];
static __device__ float g_x4[6400000];
static __device__ float g_h5[3200000];
static __device__ float g_h6[1600000];

// half gather buffers (ping-pong), rows up to 32 halves (64B)
static __device__ uint4 g_bufA[400000];
static __device__ uint4 g_bufB[400000];

static __device__ int   g_deg[N_NODES];
static __device__ int   g_row[N_NODES];
static __device__ int   g_cur[N_NODES];
static __device__ int   g_part[512];
static __device__ int   g_srcs[3500000];   // padded CSR: rows 4-aligned (<= E + 3N)
static __device__ float g_invdeg[N_NODES];
static __device__ int   g_perm[100096];    // in-tile (64) degree-sorted permutation

static __device__ unsigned g_maxx, g_minx, g_maxy, g_miny, g_maxrx, g_maxry, g_maxa;
static __device__ float g_sumx, g_sumy;

// ---------------- helpers ----------------
__device__ __forceinline__ unsigned f2o(float f) {
    unsigned u = __float_as_uint(f);
    return (u & 0x80000000u) ? ~u : (u | 0x80000000u);
}
__device__ __forceinline__ float o2f(unsigned u) {
    return (u & 0x80000000u) ? __uint_as_float(u & 0x7FFFFFFFu) : __uint_as_float(~u);
}
__device__ __forceinline__ u64 pack2(float a, float b) {
    u64 r; asm("mov.b64 %0,{%1,%2};" : "=l"(r) : "f"(a), "f"(b)); return r;
}
__device__ __forceinline__ void unpack2(u64 v, float& a, float& b) {
    asm("mov.b64 {%0,%1},%2;" : "=f"(a), "=f"(b) : "l"(v));
}
__device__ __forceinline__ u64 fma2(u64 a, u64 b, u64 c) {
    u64 d; asm("fma.rn.f32x2 %0,%1,%2,%3;" : "=l"(d) : "l"(a), "l"(b), "l"(c)); return d;
}

__device__ __forceinline__ float blockSum(float v, float* s) {
    int t = threadIdx.x;
    s[t] = v; __syncthreads();
    for (int o = 128; o > 0; o >>= 1) { if (t < o) s[t] += s[t + o]; __syncthreads(); }
    float r = s[0]; __syncthreads();
    return r;
}
__device__ __forceinline__ float blockMax(float v, float* s) {
    int t = threadIdx.x;
    s[t] = v; __syncthreads();
    for (int o = 128; o > 0; o >>= 1) { if (t < o) s[t] = fmaxf(s[t], s[t + o]); __syncthreads(); }
    float r = s[0]; __syncthreads();
    return r;
}
__device__ __forceinline__ float blockMin(float v, float* s) {
    int t = threadIdx.x;
    s[t] = v; __syncthreads();
    for (int o = 128; o > 0; o >>= 1) { if (t < o) s[t] = fminf(s[t], s[t + o]); __syncthreads(); }
    float r = s[0]; __syncthreads();
    return r;
}

// ---------------- setup kernels ----------------
__global__ void k_zero_init() {
    int i = blockIdx.x * blockDim.x + threadIdx.x;
    if (i < N_NODES) g_deg[i] = 0;
    if (i == 0) {
        g_maxx = 0u; g_maxy = 0u; g_maxrx = 0u; g_maxry = 0u; g_maxa = 0u;
        g_minx = 0xFFFFFFFFu; g_miny = 0xFFFFFFFFu;
        g_sumx = 0.f; g_sumy = 0.f;
    }
}

__global__ void __launch_bounds__(256) k_stats(const float* __restrict__ x) {
    __shared__ float s[256];
    int n = blockIdx.x * 256 + threadIdx.x;
    float X = -3.402823466e38f, Y = -3.402823466e38f, A = -3.402823466e38f;
    float Xm = 3.402823466e38f, Ym = 3.402823466e38f;
    float sx = 0.f, sy = 0.f, RX = -3.402823466e38f, RY = -3.402823466e38f;
    const float th = (float)(M_PI / 2.0);
    const float c = cosf(th), sn = sinf(th);
    if (n < N_NODES) {
        float px = x[n * 3 + 0], py = x[n * 3 + 1], pa = x[n * 3 + 2];
        X = px; Xm = px; Y = py; Ym = py; A = pa;
        sx = px; sy = py;
        RX = c * px - sn * py;
        RY = sn * px + c * py;
    }
    float bs;
    bs = blockMax(X, s);  if (threadIdx.x == 0) atomicMax(&g_maxx, f2o(bs));
    bs = blockMin(Xm, s); if (threadIdx.x == 0) atomicMin(&g_minx, f2o(bs));
    bs = blockMax(Y, s);  if (threadIdx.x == 0) atomicMax(&g_maxy, f2o(bs));
    bs = blockMin(Ym, s); if (threadIdx.x == 0) atomicMin(&g_miny, f2o(bs));
    bs = blockMax(RX, s); if (threadIdx.x == 0) atomicMax(&g_maxrx, f2o(bs));
    bs = blockMax(RY, s); if (threadIdx.x == 0) atomicMax(&g_maxry, f2o(bs));
    bs = blockMax(A, s);  if (threadIdx.x == 0) atomicMax(&g_maxa, f2o(bs));
    bs = blockSum(sx, s); if (threadIdx.x == 0) atomicAdd(&g_sumx, bs);
    bs = blockSum(sy, s); if (threadIdx.x == 0) atomicAdd(&g_sumy, bs);
}

__global__ void __launch_bounds__(256) k_normalize(const float* __restrict__ x) {
    int n = blockIdx.x * 256 + threadIdx.x;
    if (n >= N_NODES) return;
    float maxx = o2f(g_maxx), minx = o2f(g_minx);
    float maxy = o2f(g_maxy), miny = o2f(g_miny);
    float maxa = o2f(g_maxa);
    float meanx = g_sumx / (float)N_NODES, meany = g_sumy / (float)N_NODES;
    bool cond = (maxy - miny) > (maxx - minx);
    const float th = (float)(M_PI / 2.0);
    const float c = cosf(th), sn = sinf(th);
    float px = x[n * 3 + 0], py = x[n * 3 + 1], pa = x[n * 3 + 2];
    float cx, cy, mnx, mny, mxx, mxy;
    if (cond) {
        cx = c * px - sn * py;
        cy = sn * px + c * py;
        mnx = c * meanx - sn * meany;
        mny = sn * meanx + c * meany;
        mxx = o2f(g_maxrx);
        mxy = o2f(g_maxry);
    } else {
        cx = px; cy = py; mnx = meanx; mny = meany; mxx = maxx; mxy = maxy;
    }
    float4 o;
    o.x = (cx - mnx) / mxx;
    o.y = (cy - mny) / mxy;
    o.z = pa / maxa;
    o.w = 0.f;
    ((float4*)g_h0)[n] = o;
}

// ---------------- CSR build (rows padded to 4-aligned starts) ----------------
__global__ void k_count(const int* __restrict__ dst) {
    int e4 = blockIdx.x * blockDim.x + threadIdx.x;
    if (e4 * 4 < N_EDGES) {
        int4 d = ((const int4*)dst)[e4];
        atomicAdd(&g_deg[d.x], 1);
        atomicAdd(&g_deg[d.y], 1);
        atomicAdd(&g_deg[d.z], 1);
        atomicAdd(&g_deg[d.w], 1);
    }
}

// in-tile (64-node) degree sort: rank by counting; preserves line locality
__global__ void __launch_bounds__(256) k_tilesort() {
    __shared__ int sd[256];
    int t = threadIdx.x;
    int i = blockIdx.x * 256 + t;
    sd[t] = (i < N_NODES) ? g_deg[i] : 0x7FFFFFFF;
    __syncthreads();
    int tile = t >> 6, lane = t & 63;
    int base = tile << 6;
    int d = sd[base + lane];
    int rank = 0;
#pragma unroll 16
    for (int j = 0; j < 64; j++) {
        int dj = sd[base + j];
        rank += (dj < d) || (dj == d && j < lane);
    }
    g_perm[blockIdx.x * 256 + base + rank] = i;
}

__global__ void __launch_bounds__(256) k_scan1() {
    __shared__ int s[256];
    int t = threadIdx.x;
    int i = blockIdx.x * 256 + t;
    s[t] = (i < N_NODES) ? ((g_deg[i] + 3) & ~3) : 0;
    __syncthreads();
    for (int o = 128; o > 0; o >>= 1) { if (t < o) s[t] += s[t + o]; __syncthreads(); }
    if (t == 0) g_part[blockIdx.x] = s[0];
}

__global__ void __launch_bounds__(512) k_scan2() {
    __shared__ int s[512];
    int t = threadIdx.x;
    int v = (t < NBLK_N) ? g_part[t] : 0;
    s[t] = v; __syncthreads();
    for (int o = 1; o < 512; o <<= 1) {
        int a = (t >= o) ? s[t - o] : 0;
        __syncthreads();
        s[t] += a;
        __syncthreads();
    }
    if (t < NBLK_N) g_part[t] = s[t] - v;
}

__global__ void __launch_bounds__(256) k_scan3() {
    __shared__ int s[256];
    int t = threadIdx.x;
    int i = blockIdx.x * 256 + t;
    int dreal = (i < N_NODES) ? g_deg[i] : 0;
    int v = (dreal + 3) & ~3;
    s[t] = v; __syncthreads();
    for (int o = 1; o < 256; o <<= 1) {
        int a = (t >= o) ? s[t - o] : 0;
        __syncthreads();
        s[t] += a;
        __syncthreads();
    }
    if (i < N_NODES) {
        int ex = g_part[blockIdx.x] + s[t] - v;   // 4-aligned
        g_row[i] = ex;
        g_cur[i] = ex;
        g_invdeg[i] = 1.0f / (float)(dreal > 0 ? dreal : 1);
    }
}

__global__ void k_scatter(const int* __restrict__ src, const int* __restrict__ dst) {
    int e4 = blockIdx.x * blockDim.x + threadIdx.x;
    if (e4 * 4 < N_EDGES) {
        int4 d = ((const int4*)dst)[e4];
        int4 sv = ((const int4*)src)[e4];
        int p0 = atomicAdd(&g_cur[d.x], 1); g_srcs[p0] = sv.x;
        int p1 = atomicAdd(&g_cur[d.y], 1); g_srcs[p1] = sv.y;
        int p2 = atomicAdd(&g_cur[d.z], 1); g_srcs[p2] = sv.z;
        int p3 = atomicAdd(&g_cur[d.w], 1); g_srcs[p3] = sv.w;
    }
}

// ---------------- fused SAGE layer (in-tile degree-sorted order) ----------------
// TPN  = 16B chunks per gather row (threads per node in phase 1)
// F32G = gather chunks are 4 fp32 (L1 only) instead of 8 fp16
// FI   = input dim for x@wr ; FIS = fp32 row stride of xin
// FO   = output dim ; RES = residual ; PRE = gather rows already @wl
// GH   = write fp16 copy of out for next layer gather (FO halves/row)
// XFI/XFO = fused phase-3 pre-transform y = out @ xwl -> fp16 (XFI==FO)
// MLPH = fused phase-3 MLP head + softmax (L7 only; writes float2 to mout)
template <int TPN, bool F32G, int FI, int FIS, int FO, bool RES, bool PRE, bool GH,
          int XFI, int XFO, bool MLPH>
__global__ void __launch_bounds__(256) k_sage(const uint4* __restrict__ gsrc,
                                              const float* __restrict__ xin,
                                              const float* __restrict__ res,
                                              float* __restrict__ xout,
                                              const float* __restrict__ wl,
                                              const float* __restrict__ bl,
                                              const float* __restrict__ wr,
                                              const float* __restrict__ xwl,
                                              __half* __restrict__ ghout,
                                              const float* __restrict__ w1, const float* __restrict__ b1,
                                              const float* __restrict__ w2, const float* __restrict__ b2,
                                              const float* __restrict__ w3, const float* __restrict__ b3,
                                              float* __restrict__ mout) {
    constexpr int ELEM = F32G ? 4 : 8;
    constexpr int HD = TPN * ELEM;
    constexpr int NB = 256 / TPN;
    constexpr bool SOUT = (XFO > 0) || MLPH;
    __shared__ __align__(16) float s_mean[NB * HD];
    __shared__ __align__(16) float s_wl[PRE ? 2 : FI * FO];
    __shared__ __align__(16) float s_wr[FI * FO];
    __shared__ float s_bl[FO];
    __shared__ __align__(16) float s_out[SOUT ? NB * FO : 1];
    __shared__ __align__(16) float s_xwl[XFO ? XFI * XFO : 1];
    __shared__ float m_w1[MLPH ? 256 : 1], m_b1[MLPH ? 32 : 1];
    __shared__ float m_w2[MLPH ? 512 : 1], m_b2[MLPH ? 16 : 1];
    __shared__ float m_w3[MLPH ? 32 : 1], m_b3[MLPH ? 2 : 1];
    int t = threadIdx.x;
    if constexpr (!PRE) { for (int i = t; i < FI * FO; i += 256) s_wl[i] = wl[i]; }
    for (int i = t; i < FI * FO; i += 256) s_wr[i] = wr[i];
    if constexpr (XFO > 0) { for (int i = t; i < XFI * XFO; i += 256) s_xwl[i] = xwl[i]; }
    if constexpr (MLPH) {
        if (t < 256) m_w1[t] = w1[t];
        for (int i = t; i < 512; i += 256) m_w2[i] = w2[i];
        if (t < 32) { m_b1[t] = b1[t]; m_w3[t] = w3[t]; }
        if (t < 16) m_b2[t] = b2[t];
        if (t < 2) m_b3[t] = b3[t];
    }
    if (t < FO) s_bl[t] = bl[t];

    int nbase = blockIdx.x * NB;

    // ---- phase 1: mean aggregation (pipelined int4 index loads) ----
    {
        int nl = t / TPN, q = t % TPN;
        int raw = nbase + nl;
        float acc[ELEM];
#pragma unroll
        for (int k = 0; k < ELEM; k++) acc[k] = 0.f;
        if (raw < N_NODES) {
            int n = g_perm[raw];
            int start = g_row[n];                  // 4-aligned
            int dg = g_deg[n];
            const int* sp = g_srcs + start;
            int Q = dg >> 2;
            if (Q > 0) {
                int4 s4 = *(const int4*)sp;
                for (int i2 = 1; i2 < Q; i2++) {
                    int4 nx = *(const int4*)(sp + i2 * 4);   // prefetch next quad
                    uint4 v0 = gsrc[(size_t)s4.x * TPN + q];
                    uint4 v1 = gsrc[(size_t)s4.y * TPN + q];
                    uint4 v2 = gsrc[(size_t)s4.z * TPN + q];
                    uint4 v3 = gsrc[(size_t)s4.w * TPN + q];
                    if constexpr (F32G) {
                        acc[0] += __uint_as_float(v0.x) + __uint_as_float(v1.x)
                                + __uint_as_float(v2.x) + __uint_as_float(v3.x);
                        acc[1] += __uint_as_float(v0.y) + __uint_as_float(v1.y)
                                + __uint_as_float(v2.y) + __uint_as_float(v3.y);
                        acc[2] += __uint_as_float(v0.z) + __uint_as_float(v1.z)
                                + __uint_as_float(v2.z) + __uint_as_float(v3.z);
                        acc[3] += __uint_as_float(v0.w) + __uint_as_float(v1.w)
                                + __uint_as_float(v2.w) + __uint_as_float(v3.w);
                    } else {
                        const uint4* vv[4] = {&v0, &v1, &v2, &v3};
#pragma unroll
                        for (int u = 0; u < 4; u++) {
                            float2 f0 = __half22float2(*(const __half2*)&vv[u]->x);
                            float2 f1 = __half22float2(*(const __half2*)&vv[u]->y);
                            float2 f2 = __half22float2(*(const __half2*)&vv[u]->z);
                            float2 f3 = __half22float2(*(const __half2*)&vv[u]->w);
                            acc[0] += f0.x; acc[1] += f0.y;
                            acc[2] += f1.x; acc[3] += f1.y;
                            acc[4] += f2.x; acc[5] += f2.y;
                            acc[6] += f3.x; acc[7] += f3.y;
                        }
                    }
                    s4 = nx;
                }
                {   // last full quad
                    uint4 v0 = gsrc[(size_t)s4.x * TPN + q];
                    uint4 v1 = gsrc[(size_t)s4.y * TPN + q];
                    uint4 v2 = gsrc[(size_t)s4.z * TPN + q];
                    uint4 v3 = gsrc[(size_t)s4.w * TPN + q];
                    if constexpr (F32G) {
                        acc[0] += __uint_as_float(v0.x) + __uint_as_float(v1.x)
                                + __uint_as_float(v2.x) + __uint_as_float(v3.x);
                        acc[1] += __uint_as_float(v0.y) + __uint_as_float(v1.y)
                                + __uint_as_float(v2.y) + __uint_as_float(v3.y);
                        acc[2] += __uint_as_float(v0.z) + __uint_as_float(v1.z)
                                + __uint_as_float(v2.z) + __uint_as_float(v3.z);
                        acc[3] += __uint_as_float(v0.w) + __uint_as_float(v1.w)
                                + __uint_as_float(v2.w) + __uint_as_float(v3.w);
                    } else {
                        const uint4* vv[4] = {&v0, &v1, &v2, &v3};
#pragma unroll
                        for (int u = 0; u < 4; u++) {
                            float2 f0 = __half22float2(*(const __half2*)&vv[u]->x);
                            float2 f1 = __half22float2(*(const __half2*)&vv[u]->y);
                            float2 f2 = __half22float2(*(const __half2*)&vv[u]->z);
                            float2 f3 = __half22float2(*(const __half2*)&vv[u]->w);
                            acc[0] += f0.x; acc[1] += f0.y;
                            acc[2] += f1.x; acc[3] += f1.y;
                            acc[4] += f2.x; acc[5] += f2.y;
                            acc[6] += f3.x; acc[7] += f3.y;
                        }
                    }
                }
            }
            for (int e = Q * 4; e < dg; e++) {
                uint4 v = gsrc[(size_t)sp[e] * TPN + q];
                if constexpr (F32G) {
                    acc[0] += __uint_as_float(v.x);
                    acc[1] += __uint_as_float(v.y);
                    acc[2] += __uint_as_float(v.z);
                    acc[3] += __uint_as_float(v.w);
                } else {
                    float2 f0 = __half22float2(*(const __half2*)&v.x);
                    float2 f1 = __half22float2(*(const __half2*)&v.y);
                    float2 f2 = __half22float2(*(const __half2*)&v.z);
                    float2 f3 = __half22float2(*(const __half2*)&v.w);
                    acc[0] += f0.x; acc[1] += f0.y;
                    acc[2] += f1.x; acc[3] += f1.y;
                    acc[4] += f2.x; acc[5] += f2.y;
                    acc[6] += f3.x; acc[7] += f3.y;
                }
            }
            float inv = g_invdeg[n];
#pragma unroll
            for (int k = 0; k < ELEM; k++) acc[k] *= inv;
        }
#pragma unroll
        for (int k = 0; k < ELEM; k++) s_mean[nl * HD + q * ELEM + k] = acc[k];
    }
    __syncthreads();

    // ---- phase 2: out = tanh(mean@wl + bl + x@wr) [+res] ----
    constexpr int PAIRS = FO / 2;
    constexpr int NP2 = 256 / PAIRS;
    for (int p = 0; p < NB; p += NP2) {
        int nl2 = p + t / PAIRS;
        int fo2 = t % PAIRS;
        if (nl2 < NB) {
            int raw = nbase + nl2;
            if (raw < N_NODES) {
                int n = g_perm[raw];
                float b0 = s_bl[2 * fo2], b1v = s_bl[2 * fo2 + 1];
                if constexpr (PRE) {
                    b0 += s_mean[nl2 * HD + 2 * fo2];
                    b1v += s_mean[nl2 * HD + 2 * fo2 + 1];
                }
                u64 v = pack2(b0, b1v);
                const float* xr = xin + (size_t)n * FIS;
#pragma unroll
                for (int i = 0; i < FI; i++) {
                    float xi = xr[i];
                    u64 xv = pack2(xi, xi);
                    v = fma2(xv, ((const u64*)s_wr)[i * PAIRS + fo2], v);
                    if constexpr (!PRE) {
                        float mi = s_mean[nl2 * HD + i];
                        u64 mv = pack2(mi, mi);
                        v = fma2(mv, ((const u64*)s_wl)[i * PAIRS + fo2], v);
                    }
                }
                float r0, r1; unpack2(v, r0, r1);
                r0 = tanhf(r0); r1 = tanhf(r1);
                if constexpr (RES) {
                    float2 rr = ((const float2*)res)[(size_t)n * PAIRS + fo2];
                    r0 += rr.x; r1 += rr.y;
                }
                if constexpr (!MLPH) {
                    ((float2*)xout)[(size_t)n * PAIRS + fo2] = make_float2(r0, r1);
                }
                if constexpr (GH) {
                    ((__half2*)ghout)[(size_t)n * PAIRS + fo2] =
                        __float22half2_rn(make_float2(r0, r1));
                }
                if constexpr (SOUT) {
                    s_out[nl2 * FO + 2 * fo2] = r0;
                    s_out[nl2 * FO + 2 * fo2 + 1] = r1;
                }
            }
        }
    }

    // ---- phase 3a: y = out @ xwl -> fp16 gather rows for next layer ----
    if constexpr (XFO > 0) {
        __syncthreads();
        for (int base = 0; base < NB * XFO; base += 256) {
            int idx2 = base + t;
            if (idx2 < NB * XFO) {
                int nl = idx2 / XFO, fo = idx2 % XFO;
                int raw = nbase + nl;
                if (raw < N_NODES) {
                    int n = g_perm[raw];
                    float v = 0.f;
#pragma unroll
                    for (int i = 0; i < XFI; i++)
                        v += s_out[nl * XFI + i] * s_xwl[i * XFO + fo];
                    ghout[(size_t)n * XFO + fo] = __float2half_rn(v);
                }
            }
        }
    }

    // ---- phase 3b: fused MLP head + softmax (L7) ----
    if constexpr (MLPH) {
        __syncthreads();
        static_assert(!MLPH || (NB == 256 && FO == 8), "MLPH expects TPN=1, FO=8");
        int raw = nbase + t;
        if (raw < N_NODES) {
            int n = g_perm[raw];
            float in8[8];
#pragma unroll
            for (int i = 0; i < 8; i++) in8[i] = s_out[t * 8 + i];
            float a[32];
#pragma unroll
            for (int j = 0; j < 32; j++) {
                float v = m_b1[j];
#pragma unroll
                for (int i = 0; i < 8; i++) v += in8[i] * m_w1[i * 32 + j];
                a[j] = tanhf(v);
            }
            float bb[16];
#pragma unroll
            for (int j = 0; j < 16; j++) {
                float v = m_b2[j];
#pragma unroll
                for (int i = 0; i < 32; i++) v += a[i] * m_w2[i * 16 + j];
                bb[j] = tanhf(v);
            }
            float c0 = m_b3[0], c1 = m_b3[1];
#pragma unroll
            for (int i = 0; i < 16; i++) { c0 += bb[i] * m_w3[i * 2 + 0]; c1 += bb[i] * m_w3[i * 2 + 1]; }
            float m = fmaxf(c0, c1);
            float e0 = expf(c0 - m), e1 = expf(c1 - m);
            float inv = 1.f / (e0 + e1);
            ((float2*)mout)[n] = make_float2(e0 * inv, e1 * inv);
        }
    }
}

// ---------------- launch ----------------
extern "C" void kernel_launch(void* const* d_in, const int* in_sizes, int n_in,
                              void* d_out, int out_size) {
    const float* x = (const float*)d_in[0];
    const int* ei = (const int*)d_in[1];
    const int* src = ei;
    const int* dst = ei + N_EDGES;

    const float* cw[7][3];
    for (int l = 0; l < 7; l++) {
        cw[l][0] = (const float*)d_in[2 + 3 * l + 0];
        cw[l][1] = (const float*)d_in[2 + 3 * l + 1];
        cw[l][2] = (const float*)d_in[2 + 3 * l + 2];
    }
    const float* lin1_w = (const float*)d_in[23];
    const float* lin1_b = (const float*)d_in[24];
    const float* lin2_w = (const float*)d_in[25];
    const float* lin2_b = (const float*)d_in[26];
    const float* lin3_w = (const float*)d_in[27];
    const float* lin3_b = (const float*)d_in[28];
    float* out = (float*)d_out;

    float *h0, *x1, *x2, *x3, *x4, *h5, *h6;
    uint4 *bufA, *bufB;
    cudaGetSymbolAddress((void**)&h0, g_h0);
    cudaGetSymbolAddress((void**)&x1, g_x1);
    cudaGetSymbolAddress((void**)&x2, g_x2);
    cudaGetSymbolAddress((void**)&x3, g_x3);
    cudaGetSymbolAddress((void**)&x4, g_x4);
    cudaGetSymbolAddress((void**)&h5, g_h5);
    cudaGetSymbolAddress((void**)&h6, g_h6);
    cudaGetSymbolAddress((void**)&bufA, g_bufA);
    cudaGetSymbolAddress((void**)&bufB, g_bufB);
    __half* hA = (__half*)bufA;
    __half* hB = (__half*)bufB;

    // setup + CSR build + in-tile degree sort
    k_zero_init<<<NBLK_N, 256>>>();
    k_stats<<<NBLK_N, 256>>>(x);
    k_normalize<<<NBLK_N, 256>>>(x);
    k_count<<<3125, 256>>>(dst);
    k_tilesort<<<NBLK_N, 256>>>();
    k_scan1<<<NBLK_N, 256>>>();
    k_scan2<<<1, 512>>>();
    k_scan3<<<NBLK_N, 256>>>();
    k_scatter<<<3125, 256>>>(src, dst);

    // L1: 3->8   gather h0 fp32 (TPN=1) -> x1 + x1h(B)
    k_sage<1, true, 3, 4, 8, false, false, true, 0, 0, false><<<391, 256>>>(
        (const uint4*)h0, h0, nullptr, x1, cw[0][0], cw[0][1], cw[0][2], nullptr, hB,
        nullptr, nullptr, nullptr, nullptr, nullptr, nullptr, nullptr);
    // L2: 8->16  gather x1h(B) -> x2 + x2h(A)
    k_sage<1, false, 8, 8, 16, false, false, true, 0, 0, false><<<391, 256>>>(
        bufB, x1, nullptr, x2, cw[1][0], cw[1][1], cw[1][2], nullptr, hA,
        nullptr, nullptr, nullptr, nullptr, nullptr, nullptr, nullptr);
    // L3: 16->32 gather x2h(A) -> x3 + x3h(B)
    k_sage<2, false, 16, 16, 32, false, false, true, 0, 0, false><<<782, 256>>>(
        bufA, x2, nullptr, x3, cw[2][0], cw[2][1], cw[2][2], nullptr, hB,
        nullptr, nullptr, nullptr, nullptr, nullptr, nullptr, nullptr);
    // L4: 32->64 gather x3h(B) -> x4 ; phase3 y5 = x4@wl5 (64->32) -> A
    k_sage<4, false, 32, 32, 64, false, false, false, 64, 32, false><<<1563, 256>>>(
        bufB, x3, nullptr, x4, cw[3][0], cw[3][1], cw[3][2], cw[4][0], hA,
        nullptr, nullptr, nullptr, nullptr, nullptr, nullptr, nullptr);
    // L5: (PRE) gather y5h(A), self x4(64), res x3 -> h5 ; phase3 y6 = h5@wl6 (32->16) -> B
    k_sage<4, false, 64, 64, 32, true, true, false, 32, 16, false><<<1563, 256>>>(
        bufA, x4, x3, h5, cw[4][0], cw[4][1], cw[4][2], cw[5][0], hB,
        nullptr, nullptr, nullptr, nullptr, nullptr, nullptr, nullptr);
    // L6: (PRE) gather y6h(B), self h5(32), res x2 -> h6 ; phase3 y7 = h6@wl7 (16->8) -> A
    k_sage<2, false, 32, 32, 16, true, true, false, 16, 8, false><<<782, 256>>>(
        bufB, h5, x2, h6, cw[5][0], cw[5][1], cw[5][2], cw[6][0], hA,
        nullptr, nullptr, nullptr, nullptr, nullptr, nullptr, nullptr);
    // L7: (PRE) gather y7h(A), self h6(16), res x1 ; fused MLP head -> out
    k_sage<1, false, 16, 16, 8, true, true, false, 0, 0, true><<<391, 256>>>(
        bufA, h6, x1, nullptr, cw[6][0], cw[6][1], cw[6][2], nullptr, nullptr,
        lin1_w, lin1_b, lin2_w, lin2_b, lin3_w, lin3_b, out);
}

// round 10
// speedup vs baseline: 1.0609x; 1.0609x over previous
#include <cuda_runtime.h>
#include <cuda_fp16.h>
#include <math.h>

#define N_NODES 100000
#define N_EDGES 3200000
#define NBLK_N 391
#define NBLK_S 1563   // ceil(100000/64)

typedef unsigned long long u64;

// ---------------- static device scratch (allocation-free) ----------------
static __device__ float g_h0[400000];      // fp32, stride 4 (L1 gather; fp16 would overflow)
static __device__ float g_x1[800000];
static __device__ float g_x2[1600000];
static __device__ float g_x3[3200000];
static __device__ float g_x4[6400000];
static __device__ float g_h5[3200000];
static __device__ float g_h6[1600000];

// half gather buffers (ping-pong), rows up to 32 halves (64B)
static __device__ uint4 g_bufA[400000];
static __device__ uint4 g_bufB[400000];

static __device__ int   g_deg[N_NODES];
static __device__ int   g_row[N_NODES];
static __device__ int   g_cur[N_NODES];
static __device__ int   g_part[512];
static __device__ int   g_srcs[3500000];   // padded CSR: rows 4-aligned (<= E + 3N)
static __device__ float g_invdeg[N_NODES];

static __device__ unsigned g_maxx, g_minx, g_maxy, g_miny, g_maxrx, g_maxry, g_maxa;
static __device__ float g_sumx, g_sumy;

// ---------------- helpers ----------------
__device__ __forceinline__ unsigned f2o(float f) {
    unsigned u = __float_as_uint(f);
    return (u & 0x80000000u) ? ~u : (u | 0x80000000u);
}
__device__ __forceinline__ float o2f(unsigned u) {
    return (u & 0x80000000u) ? __uint_as_float(u & 0x7FFFFFFFu) : __uint_as_float(~u);
}
__device__ __forceinline__ u64 pack2(float a, float b) {
    u64 r; asm("mov.b64 %0,{%1,%2};" : "=l"(r) : "f"(a), "f"(b)); return r;
}
__device__ __forceinline__ void unpack2(u64 v, float& a, float& b) {
    asm("mov.b64 {%0,%1},%2;" : "=f"(a), "=f"(b) : "l"(v));
}
__device__ __forceinline__ u64 fma2(u64 a, u64 b, u64 c) {
    u64 d; asm("fma.rn.f32x2 %0,%1,%2,%3;" : "=l"(d) : "l"(a), "l"(b), "l"(c)); return d;
}

__device__ __forceinline__ float blockSum(float v, float* s) {
    int t = threadIdx.x;
    s[t] = v; __syncthreads();
    for (int o = 128; o > 0; o >>= 1) { if (t < o) s[t] += s[t + o]; __syncthreads(); }
    float r = s[0]; __syncthreads();
    return r;
}
__device__ __forceinline__ float blockMax(float v, float* s) {
    int t = threadIdx.x;
    s[t] = v; __syncthreads();
    for (int o = 128; o > 0; o >>= 1) { if (t < o) s[t] = fmaxf(s[t], s[t + o]); __syncthreads(); }
    float r = s[0]; __syncthreads();
    return r;
}
__device__ __forceinline__ float blockMin(float v, float* s) {
    int t = threadIdx.x;
    s[t] = v; __syncthreads();
    for (int o = 128; o > 0; o >>= 1) { if (t < o) s[t] = fminf(s[t], s[t + o]); __syncthreads(); }
    float r = s[0]; __syncthreads();
    return r;
}

// ---------------- setup kernels ----------------
__global__ void k_zero_init() {
    int i = blockIdx.x * blockDim.x + threadIdx.x;
    if (i < N_NODES) g_deg[i] = 0;
    if (i == 0) {
        g_maxx = 0u; g_maxy = 0u; g_maxrx = 0u; g_maxry = 0u; g_maxa = 0u;
        g_minx = 0xFFFFFFFFu; g_miny = 0xFFFFFFFFu;
        g_sumx = 0.f; g_sumy = 0.f;
    }
}

__global__ void __launch_bounds__(256) k_stats(const float* __restrict__ x) {
    __shared__ float s[256];
    int n = blockIdx.x * 256 + threadIdx.x;
    float X = -3.402823466e38f, Y = -3.402823466e38f, A = -3.402823466e38f;
    float Xm = 3.402823466e38f, Ym = 3.402823466e38f;
    float sx = 0.f, sy = 0.f, RX = -3.402823466e38f, RY = -3.402823466e38f;
    const float th = (float)(M_PI / 2.0);
    const float c = cosf(th), sn = sinf(th);
    if (n < N_NODES) {
        float px = x[n * 3 + 0], py = x[n * 3 + 1], pa = x[n * 3 + 2];
        X = px; Xm = px; Y = py; Ym = py; A = pa;
        sx = px; sy = py;
        RX = c * px - sn * py;
        RY = sn * px + c * py;
    }
    float bs;
    bs = blockMax(X, s);  if (threadIdx.x == 0) atomicMax(&g_maxx, f2o(bs));
    bs = blockMin(Xm, s); if (threadIdx.x == 0) atomicMin(&g_minx, f2o(bs));
    bs = blockMax(Y, s);  if (threadIdx.x == 0) atomicMax(&g_maxy, f2o(bs));
    bs = blockMin(Ym, s); if (threadIdx.x == 0) atomicMin(&g_miny, f2o(bs));
    bs = blockMax(RX, s); if (threadIdx.x == 0) atomicMax(&g_maxrx, f2o(bs));
    bs = blockMax(RY, s); if (threadIdx.x == 0) atomicMax(&g_maxry, f2o(bs));
    bs = blockMax(A, s);  if (threadIdx.x == 0) atomicMax(&g_maxa, f2o(bs));
    bs = blockSum(sx, s); if (threadIdx.x == 0) atomicAdd(&g_sumx, bs);
    bs = blockSum(sy, s); if (threadIdx.x == 0) atomicAdd(&g_sumy, bs);
}

__global__ void __launch_bounds__(256) k_normalize(const float* __restrict__ x) {
    int n = blockIdx.x * 256 + threadIdx.x;
    if (n >= N_NODES) return;
    float maxx = o2f(g_maxx), minx = o2f(g_minx);
    float maxy = o2f(g_maxy), miny = o2f(g_miny);
    float maxa = o2f(g_maxa);
    float meanx = g_sumx / (float)N_NODES, meany = g_sumy / (float)N_NODES;
    bool cond = (maxy - miny) > (maxx - minx);
    const float th = (float)(M_PI / 2.0);
    const float c = cosf(th), sn = sinf(th);
    float px = x[n * 3 + 0], py = x[n * 3 + 1], pa = x[n * 3 + 2];
    float cx, cy, mnx, mny, mxx, mxy;
    if (cond) {
        cx = c * px - sn * py;
        cy = sn * px + c * py;
        mnx = c * meanx - sn * meany;
        mny = sn * meanx + c * meany;
        mxx = o2f(g_maxrx);
        mxy = o2f(g_maxry);
    } else {
        cx = px; cy = py; mnx = meanx; mny = meany; mxx = maxx; mxy = maxy;
    }
    float4 o;
    o.x = (cx - mnx) / mxx;
    o.y = (cy - mny) / mxy;
    o.z = pa / maxa;
    o.w = 0.f;
    ((float4*)g_h0)[n] = o;
}

// ---------------- CSR build (rows padded to 4-aligned starts) ----------------
__global__ void k_count(const int* __restrict__ dst) {
    int e4 = blockIdx.x * blockDim.x + threadIdx.x;
    if (e4 * 4 < N_EDGES) {
        int4 d = ((const int4*)dst)[e4];
        atomicAdd(&g_deg[d.x], 1);
        atomicAdd(&g_deg[d.y], 1);
        atomicAdd(&g_deg[d.z], 1);
        atomicAdd(&g_deg[d.w], 1);
    }
}

__global__ void __launch_bounds__(256) k_scan1() {
    __shared__ int s[256];
    int t = threadIdx.x;
    int i = blockIdx.x * 256 + t;
    s[t] = (i < N_NODES) ? ((g_deg[i] + 3) & ~3) : 0;
    __syncthreads();
    for (int o = 128; o > 0; o >>= 1) { if (t < o) s[t] += s[t + o]; __syncthreads(); }
    if (t == 0) g_part[blockIdx.x] = s[0];
}

__global__ void __launch_bounds__(512) k_scan2() {
    __shared__ int s[512];
    int t = threadIdx.x;
    int v = (t < NBLK_N) ? g_part[t] : 0;
    s[t] = v; __syncthreads();
    for (int o = 1; o < 512; o <<= 1) {
        int a = (t >= o) ? s[t - o] : 0;
        __syncthreads();
        s[t] += a;
        __syncthreads();
    }
    if (t < NBLK_N) g_part[t] = s[t] - v;
}

__global__ void __launch_bounds__(256) k_scan3() {
    __shared__ int s[256];
    int t = threadIdx.x;
    int i = blockIdx.x * 256 + t;
    int dreal = (i < N_NODES) ? g_deg[i] : 0;
    int v = (dreal + 3) & ~3;
    s[t] = v; __syncthreads();
    for (int o = 1; o < 256; o <<= 1) {
        int a = (t >= o) ? s[t - o] : 0;
        __syncthreads();
        s[t] += a;
        __syncthreads();
    }
    if (i < N_NODES) {
        int ex = g_part[blockIdx.x] + s[t] - v;   // 4-aligned
        g_row[i] = ex;
        g_cur[i] = ex;
        g_invdeg[i] = 1.0f / (float)(dreal > 0 ? dreal : 1);
    }
}

__global__ void k_scatter(const int* __restrict__ src, const int* __restrict__ dst) {
    int e4 = blockIdx.x * blockDim.x + threadIdx.x;
    if (e4 * 4 < N_EDGES) {
        int4 d = ((const int4*)dst)[e4];
        int4 sv = ((const int4*)src)[e4];
        int p0 = atomicAdd(&g_cur[d.x], 1); g_srcs[p0] = sv.x;
        int p1 = atomicAdd(&g_cur[d.y], 1); g_srcs[p1] = sv.y;
        int p2 = atomicAdd(&g_cur[d.z], 1); g_srcs[p2] = sv.z;
        int p3 = atomicAdd(&g_cur[d.w], 1); g_srcs[p3] = sv.w;
    }
}

// ---------------- gather one row's chunk into acc ----------------
template <bool F32G, int TPN, int ELEM>
__device__ __forceinline__ void gacc(const uint4* __restrict__ gsrc, int idx, int q,
                                     float (&acc)[ELEM]) {
    uint4 v = gsrc[(size_t)idx * TPN + q];
    if constexpr (F32G) {
        acc[0] += __uint_as_float(v.x);
        acc[1] += __uint_as_float(v.y);
        acc[2] += __uint_as_float(v.z);
        acc[3] += __uint_as_float(v.w);
    } else {
        float2 f0 = __half22float2(*(const __half2*)&v.x);
        float2 f1 = __half22float2(*(const __half2*)&v.y);
        float2 f2 = __half22float2(*(const __half2*)&v.z);
        float2 f3 = __half22float2(*(const __half2*)&v.w);
        acc[0] += f0.x; acc[1] += f0.y;
        acc[2] += f1.x; acc[3] += f1.y;
        acc[4] += f2.x; acc[5] += f2.y;
        acc[6] += f3.x; acc[7] += f3.y;
    }
}

// ---------------- fused SAGE layer (4-thread node groups: TPN chunks x ES splits) ----
// TPN  = 16B chunks per gather row ; ES = edge-split factor ; TPN*ES == 4
// F32G = gather chunks are 4 fp32 (L1 only) instead of 8 fp16
// FI   = input dim for x@wr ; FIS = fp32 row stride of xin
// FO   = output dim ; RES = residual ; PRE = gather rows already @wl
// GH   = write fp16 copy of out for next layer gather (FO halves/row)
// XFI/XFO = fused phase-3 pre-transform y = out @ xwl -> fp16 (XFI==FO)
// MLPH = fused phase-3 MLP head + softmax (L7 only; writes float2 to mout)
template <int TPN, int ES, bool F32G, int FI, int FIS, int FO, bool RES, bool PRE, bool GH,
          int XFI, int XFO, bool MLPH>
__global__ void __launch_bounds__(256) k_sage(const uint4* __restrict__ gsrc,
                                              const float* __restrict__ xin,
                                              const float* __restrict__ res,
                                              float* __restrict__ xout,
                                              const float* __restrict__ wl,
                                              const float* __restrict__ bl,
                                              const float* __restrict__ wr,
                                              const float* __restrict__ xwl,
                                              __half* __restrict__ ghout,
                                              const float* __restrict__ w1, const float* __restrict__ b1,
                                              const float* __restrict__ w2, const float* __restrict__ b2,
                                              const float* __restrict__ w3, const float* __restrict__ b3,
                                              float* __restrict__ mout) {
    static_assert(TPN * ES == 4, "4-thread node groups");
    constexpr int ELEM = F32G ? 4 : 8;
    constexpr int HD = TPN * ELEM;
    constexpr int NB = 64;              // nodes per block (4 threads each)
    constexpr bool SOUT = (XFO > 0) || MLPH;
    __shared__ __align__(16) float s_mean[NB * HD];
    __shared__ __align__(16) float s_wl[PRE ? 2 : FI * FO];
    __shared__ __align__(16) float s_wr[FI * FO];
    __shared__ float s_bl[FO];
    __shared__ __align__(16) float s_out[SOUT ? NB * FO : 1];
    __shared__ __align__(16) float s_xwl[XFO ? XFI * XFO : 1];
    __shared__ float m_w1[MLPH ? 256 : 1], m_b1[MLPH ? 32 : 1];
    __shared__ float m_w2[MLPH ? 512 : 1], m_b2[MLPH ? 16 : 1];
    __shared__ float m_w3[MLPH ? 32 : 1], m_b3[MLPH ? 2 : 1];
    int t = threadIdx.x;
    if constexpr (!PRE) { for (int i = t; i < FI * FO; i += 256) s_wl[i] = wl[i]; }
    for (int i = t; i < FI * FO; i += 256) s_wr[i] = wr[i];
    if constexpr (XFO > 0) { for (int i = t; i < XFI * XFO; i += 256) s_xwl[i] = xwl[i]; }
    if constexpr (MLPH) {
        if (t < 256) m_w1[t] = w1[t];
        for (int i = t; i < 512; i += 256) m_w2[i] = w2[i];
        if (t < 32) { m_b1[t] = b1[t]; m_w3[t] = w3[t]; }
        if (t < 16) m_b2[t] = b2[t];
        if (t < 2) m_b3[t] = b3[t];
    }
    if (t < FO) s_bl[t] = bl[t];

    int nbase = blockIdx.x * NB;

    // ---- phase 1: mean aggregation; per node: TPN chunk-threads x ES edge-split ----
    {
        int nl = t >> 2;
        int sub = t & 3;
        int q = sub % TPN;
        int es = sub / TPN;
        int n = nbase + nl;
        float acc[ELEM];
#pragma unroll
        for (int k = 0; k < ELEM; k++) acc[k] = 0.f;
        int dg = 0;
        if (n < N_NODES) {
            int start = g_row[n];                  // 4-aligned
            dg = g_deg[n];
            const int* sp = g_srcs + start;
            int Q = dg >> 2;
            int nq = (Q > es) ? ((Q - es + ES - 1) / ES) : 0;  // quads for this split
            if (nq > 0) {
                const int4* qp = (const int4*)sp + es;
                int4 s4 = qp[0];
                for (int i2 = 1; i2 < nq; i2++) {
                    int4 nx = qp[(size_t)i2 * ES];            // prefetch next quad
                    gacc<F32G, TPN, ELEM>(gsrc, s4.x, q, acc);
                    gacc<F32G, TPN, ELEM>(gsrc, s4.y, q, acc);
                    gacc<F32G, TPN, ELEM>(gsrc, s4.z, q, acc);
                    gacc<F32G, TPN, ELEM>(gsrc, s4.w, q, acc);
                    s4 = nx;
                }
                gacc<F32G, TPN, ELEM>(gsrc, s4.x, q, acc);
                gacc<F32G, TPN, ELEM>(gsrc, s4.y, q, acc);
                gacc<F32G, TPN, ELEM>(gsrc, s4.z, q, acc);
                gacc<F32G, TPN, ELEM>(gsrc, s4.w, q, acc);
            }
            if (es == 0) {
                for (int e = Q * 4; e < dg; e++)
                    gacc<F32G, TPN, ELEM>(gsrc, sp[e], q, acc);
            }
        }
        // reduce across edge-split lanes (stride TPN within the 4-lane group)
#pragma unroll
        for (int off = TPN; off < 4; off <<= 1) {
#pragma unroll
            for (int k = 0; k < ELEM; k++)
                acc[k] += __shfl_xor_sync(0xffffffffu, acc[k], off);
        }
        if (n < N_NODES && es == 0) {
            float inv = g_invdeg[n];
#pragma unroll
            for (int k = 0; k < ELEM; k++)
                s_mean[nl * HD + q * ELEM + k] = acc[k] * inv;
        }
    }
    __syncthreads();

    // ---- phase 2: out = tanh(mean@wl + bl + x@wr) [+res] ----
    constexpr int PAIRS = FO / 2;
    constexpr int NP2 = 256 / PAIRS;
    for (int p = 0; p < NB; p += NP2) {
        int nl2 = p + t / PAIRS;
        int fo2 = t % PAIRS;
        if (nl2 < NB) {
            int n = nbase + nl2;
            if (n < N_NODES) {
                float b0 = s_bl[2 * fo2], b1v = s_bl[2 * fo2 + 1];
                if constexpr (PRE) {
                    b0 += s_mean[nl2 * HD + 2 * fo2];
                    b1v += s_mean[nl2 * HD + 2 * fo2 + 1];
                }
                u64 v = pack2(b0, b1v);
                const float* xr = xin + (size_t)n * FIS;
#pragma unroll
                for (int i = 0; i < FI; i++) {
                    float xi = xr[i];
                    u64 xv = pack2(xi, xi);
                    v = fma2(xv, ((const u64*)s_wr)[i * PAIRS + fo2], v);
                    if constexpr (!PRE) {
                        float mi = s_mean[nl2 * HD + i];
                        u64 mv = pack2(mi, mi);
                        v = fma2(mv, ((const u64*)s_wl)[i * PAIRS + fo2], v);
                    }
                }
                float r0, r1; unpack2(v, r0, r1);
                r0 = tanhf(r0); r1 = tanhf(r1);
                if constexpr (RES) {
                    float2 rr = ((const float2*)res)[(size_t)n * PAIRS + fo2];
                    r0 += rr.x; r1 += rr.y;
                }
                if constexpr (!MLPH) {
                    ((float2*)xout)[(size_t)n * PAIRS + fo2] = make_float2(r0, r1);
                }
                if constexpr (GH) {
                    ((__half2*)ghout)[(size_t)n * PAIRS + fo2] =
                        __float22half2_rn(make_float2(r0, r1));
                }
                if constexpr (SOUT) {
                    s_out[nl2 * FO + 2 * fo2] = r0;
                    s_out[nl2 * FO + 2 * fo2 + 1] = r1;
                }
            }
        }
    }

    // ---- phase 3a: y = out @ xwl -> fp16 gather rows for next layer ----
    if constexpr (XFO > 0) {
        __syncthreads();
        for (int base = 0; base < NB * XFO; base += 256) {
            int idx2 = base + t;
            if (idx2 < NB * XFO) {
                int nl = idx2 / XFO, fo = idx2 % XFO;
                int n = nbase + nl;
                if (n < N_NODES) {
                    float v = 0.f;
#pragma unroll
                    for (int i = 0; i < XFI; i++)
                        v += s_out[nl * XFI + i] * s_xwl[i * XFO + fo];
                    ghout[(size_t)n * XFO + fo] = __float2half_rn(v);
                }
            }
        }
    }

    // ---- phase 3b: fused MLP head + softmax (L7) ----
    if constexpr (MLPH) {
        __syncthreads();
        if (t < NB) {
            int n = nbase + t;
            if (n < N_NODES) {
                float in8[8];
#pragma unroll
                for (int i = 0; i < 8; i++) in8[i] = s_out[t * 8 + i];
                float a[32];
#pragma unroll
                for (int j = 0; j < 32; j++) {
                    float v = m_b1[j];
#pragma unroll
                    for (int i = 0; i < 8; i++) v += in8[i] * m_w1[i * 32 + j];
                    a[j] = tanhf(v);
                }
                float bb[16];
#pragma unroll
                for (int j = 0; j < 16; j++) {
                    float v = m_b2[j];
#pragma unroll
                    for (int i = 0; i < 32; i++) v += a[i] * m_w2[i * 16 + j];
                    bb[j] = tanhf(v);
                }
                float c0 = m_b3[0], c1 = m_b3[1];
#pragma unroll
                for (int i = 0; i < 16; i++) { c0 += bb[i] * m_w3[i * 2 + 0]; c1 += bb[i] * m_w3[i * 2 + 1]; }
                float m = fmaxf(c0, c1);
                float e0 = expf(c0 - m), e1 = expf(c1 - m);
                float inv = 1.f / (e0 + e1);
                ((float2*)mout)[n] = make_float2(e0 * inv, e1 * inv);
            }
        }
    }
}

// ---------------- launch ----------------
extern "C" void kernel_launch(void* const* d_in, const int* in_sizes, int n_in,
                              void* d_out, int out_size) {
    const float* x = (const float*)d_in[0];
    const int* ei = (const int*)d_in[1];
    const int* src = ei;
    const int* dst = ei + N_EDGES;

    const float* cw[7][3];
    for (int l = 0; l < 7; l++) {
        cw[l][0] = (const float*)d_in[2 + 3 * l + 0];
        cw[l][1] = (const float*)d_in[2 + 3 * l + 1];
        cw[l][2] = (const float*)d_in[2 + 3 * l + 2];
    }
    const float* lin1_w = (const float*)d_in[23];
    const float* lin1_b = (const float*)d_in[24];
    const float* lin2_w = (const float*)d_in[25];
    const float* lin2_b = (const float*)d_in[26];
    const float* lin3_w = (const float*)d_in[27];
    const float* lin3_b = (const float*)d_in[28];
    float* out = (float*)d_out;

    float *h0, *x1, *x2, *x3, *x4, *h5, *h6;
    uint4 *bufA, *bufB;
    cudaGetSymbolAddress((void**)&h0, g_h0);
    cudaGetSymbolAddress((void**)&x1, g_x1);
    cudaGetSymbolAddress((void**)&x2, g_x2);
    cudaGetSymbolAddress((void**)&x3, g_x3);
    cudaGetSymbolAddress((void**)&x4, g_x4);
    cudaGetSymbolAddress((void**)&h5, g_h5);
    cudaGetSymbolAddress((void**)&h6, g_h6);
    cudaGetSymbolAddress((void**)&bufA, g_bufA);
    cudaGetSymbolAddress((void**)&bufB, g_bufB);
    __half* hA = (__half*)bufA;
    __half* hB = (__half*)bufB;

    // setup + CSR build
    k_zero_init<<<NBLK_N, 256>>>();
    k_stats<<<NBLK_N, 256>>>(x);
    k_normalize<<<NBLK_N, 256>>>(x);
    k_count<<<3125, 256>>>(dst);
    k_scan1<<<NBLK_N, 256>>>();
    k_scan2<<<1, 512>>>();
    k_scan3<<<NBLK_N, 256>>>();
    k_scatter<<<3125, 256>>>(src, dst);

    // L1: 3->8   gather h0 fp32 (TPN=1,ES=4) -> x1 + x1h(B)
    k_sage<1, 4, true, 3, 4, 8, false, false, true, 0, 0, false><<<NBLK_S, 256>>>(
        (const uint4*)h0, h0, nullptr, x1, cw[0][0], cw[0][1], cw[0][2], nullptr, hB,
        nullptr, nullptr, nullptr, nullptr, nullptr, nullptr, nullptr);
    // L2: 8->16  gather x1h(B) (TPN=1,ES=4) -> x2 + x2h(A)
    k_sage<1, 4, false, 8, 8, 16, false, false, true, 0, 0, false><<<NBLK_S, 256>>>(
        bufB, x1, nullptr, x2, cw[1][0], cw[1][1], cw[1][2], nullptr, hA,
        nullptr, nullptr, nullptr, nullptr, nullptr, nullptr, nullptr);
    // L3: 16->32 gather x2h(A) (TPN=2,ES=2) -> x3 + x3h(B)
    k_sage<2, 2, false, 16, 16, 32, false, false, true, 0, 0, false><<<NBLK_S, 256>>>(
        bufA, x2, nullptr, x3, cw[2][0], cw[2][1], cw[2][2], nullptr, hB,
        nullptr, nullptr, nullptr, nullptr, nullptr, nullptr, nullptr);
    // L4: 32->64 gather x3h(B) (TPN=4,ES=1) -> x4 ; phase3 y5 = x4@wl5 (64->32) -> A
    k_sage<4, 1, false, 32, 32, 64, false, false, false, 64, 32, false><<<NBLK_S, 256>>>(
        bufB, x3, nullptr, x4, cw[3][0], cw[3][1], cw[3][2], cw[4][0], hA,
        nullptr, nullptr, nullptr, nullptr, nullptr, nullptr, nullptr);
    // L5: (PRE) gather y5h(A) (TPN=4,ES=1), self x4(64), res x3 -> h5 ; y6 = h5@wl6 -> B
    k_sage<4, 1, false, 64, 64, 32, true, true, false, 32, 16, false><<<NBLK_S, 256>>>(
        bufA, x4, x3, h5, cw[4][0], cw[4][1], cw[4][2], cw[5][0], hB,
        nullptr, nullptr, nullptr, nullptr, nullptr, nullptr, nullptr);
    // L6: (PRE) gather y6h(B) (TPN=2,ES=2), self h5(32), res x2 -> h6 ; y7 = h6@wl7 -> A
    k_sage<2, 2, false, 32, 32, 16, true, true, false, 16, 8, false><<<NBLK_S, 256>>>(
        bufB, h5, x2, h6, cw[5][0], cw[5][1], cw[5][2], cw[6][0], hA,
        nullptr, nullptr, nullptr, nullptr, nullptr, nullptr, nullptr);
    // L7: (PRE) gather y7h(A) (TPN=1,ES=4), self h6(16), res x1 ; fused MLP head -> out
    k_sage<1, 4, false, 16, 16, 8, true, true, false, 0, 0, true><<<NBLK_S, 256>>>(
        bufA, h6, x1, nullptr, cw[6][0], cw[6][1], cw[6][2], nullptr, nullptr,
        lin1_w, lin1_b, lin2_w, lin2_b, lin3_w, lin3_b, out);
}

// round 11
// speedup vs baseline: 1.0763x; 1.0145x over previous
#include <cuda_runtime.h>
#include <cuda_fp16.h>
#include <math.h>

#define N_NODES 100000
#define N_EDGES 3200000
#define NBLK_N 391
#define NBLK_E4 3125
#define NBLK_S 1563   // ceil(100000/64)

typedef unsigned long long u64;

// ---------------- static device scratch (allocation-free) ----------------
static __device__ float g_h0[400000];      // fp32, stride 4 (L1 gather; fp16 would overflow)
static __device__ float g_x1[800000];
static __device__ float g_x2[1600000];
static __device__ float g_x3[3200000];
static __device__ float g_x4[6400000];
static __device__ float g_h5[3200000];
static __device__ float g_h6[1600000];

// half gather buffers (ping-pong), rows up to 32 halves (64B)
static __device__ uint4 g_bufA[400000];
static __device__ uint4 g_bufB[400000];

static __device__ int   g_deg[N_NODES];
static __device__ int   g_row[N_NODES];
static __device__ int   g_cur[N_NODES];
static __device__ int   g_part[512];
static __device__ int   g_srcs[3500000];   // padded CSR: rows 4-aligned (<= E + 3N)
static __device__ float g_invdeg[N_NODES];

static __device__ unsigned g_maxx, g_minx, g_maxy, g_miny, g_maxrx, g_maxry, g_maxa;
static __device__ float g_sumx, g_sumy;

// ---------------- helpers ----------------
__device__ __forceinline__ unsigned f2o(float f) {
    unsigned u = __float_as_uint(f);
    return (u & 0x80000000u) ? ~u : (u | 0x80000000u);
}
__device__ __forceinline__ float o2f(unsigned u) {
    return (u & 0x80000000u) ? __uint_as_float(u & 0x7FFFFFFFu) : __uint_as_float(~u);
}
__device__ __forceinline__ u64 pack2(float a, float b) {
    u64 r; asm("mov.b64 %0,{%1,%2};" : "=l"(r) : "f"(a), "f"(b)); return r;
}
__device__ __forceinline__ void unpack2(u64 v, float& a, float& b) {
    asm("mov.b64 {%0,%1},%2;" : "=f"(a), "=f"(b) : "l"(v));
}
__device__ __forceinline__ u64 fma2(u64 a, u64 b, u64 c) {
    u64 d; asm("fma.rn.f32x2 %0,%1,%2,%3;" : "=l"(d) : "l"(a), "l"(b), "l"(c)); return d;
}

__device__ __forceinline__ float blockSum(float v, float* s) {
    int t = threadIdx.x;
    s[t] = v; __syncthreads();
    for (int o = 128; o > 0; o >>= 1) { if (t < o) s[t] += s[t + o]; __syncthreads(); }
    float r = s[0]; __syncthreads();
    return r;
}
__device__ __forceinline__ float blockMax(float v, float* s) {
    int t = threadIdx.x;
    s[t] = v; __syncthreads();
    for (int o = 128; o > 0; o >>= 1) { if (t < o) s[t] = fmaxf(s[t], s[t + o]); __syncthreads(); }
    float r = s[0]; __syncthreads();
    return r;
}
__device__ __forceinline__ float blockMin(float v, float* s) {
    int t = threadIdx.x;
    s[t] = v; __syncthreads();
    for (int o = 128; o > 0; o >>= 1) { if (t < o) s[t] = fminf(s[t], s[t + o]); __syncthreads(); }
    float r = s[0]; __syncthreads();
    return r;
}

// ---------------- setup kernels ----------------
__global__ void k_zero_init() {
    int i = blockIdx.x * blockDim.x + threadIdx.x;
    if (i < N_NODES) g_deg[i] = 0;
    if (i == 0) {
        g_maxx = 0u; g_maxy = 0u; g_maxrx = 0u; g_maxry = 0u; g_maxa = 0u;
        g_minx = 0xFFFFFFFFu; g_miny = 0xFFFFFFFFu;
        g_sumx = 0.f; g_sumy = 0.f;
    }
}

// fused: edge-degree count (all blocks) + coordinate stats (blocks < NBLK_N)
__global__ void __launch_bounds__(256) k_count_stats(const int* __restrict__ dst,
                                                     const float* __restrict__ x) {
    __shared__ float s[256];
    int e4 = blockIdx.x * 256 + threadIdx.x;
    if (e4 * 4 < N_EDGES) {
        int4 d = ((const int4*)dst)[e4];
        atomicAdd(&g_deg[d.x], 1);
        atomicAdd(&g_deg[d.y], 1);
        atomicAdd(&g_deg[d.z], 1);
        atomicAdd(&g_deg[d.w], 1);
    }
    if (blockIdx.x >= NBLK_N) return;

    int n = blockIdx.x * 256 + threadIdx.x;
    float X = -3.402823466e38f, Y = -3.402823466e38f, A = -3.402823466e38f;
    float Xm = 3.402823466e38f, Ym = 3.402823466e38f;
    float sx = 0.f, sy = 0.f, RX = -3.402823466e38f, RY = -3.402823466e38f;
    const float th = (float)(M_PI / 2.0);
    const float c = cosf(th), sn = sinf(th);
    if (n < N_NODES) {
        float px = x[n * 3 + 0], py = x[n * 3 + 1], pa = x[n * 3 + 2];
        X = px; Xm = px; Y = py; Ym = py; A = pa;
        sx = px; sy = py;
        RX = c * px - sn * py;
        RY = sn * px + c * py;
    }
    float bs;
    bs = blockMax(X, s);  if (threadIdx.x == 0) atomicMax(&g_maxx, f2o(bs));
    bs = blockMin(Xm, s); if (threadIdx.x == 0) atomicMin(&g_minx, f2o(bs));
    bs = blockMax(Y, s);  if (threadIdx.x == 0) atomicMax(&g_maxy, f2o(bs));
    bs = blockMin(Ym, s); if (threadIdx.x == 0) atomicMin(&g_miny, f2o(bs));
    bs = blockMax(RX, s); if (threadIdx.x == 0) atomicMax(&g_maxrx, f2o(bs));
    bs = blockMax(RY, s); if (threadIdx.x == 0) atomicMax(&g_maxry, f2o(bs));
    bs = blockMax(A, s);  if (threadIdx.x == 0) atomicMax(&g_maxa, f2o(bs));
    bs = blockSum(sx, s); if (threadIdx.x == 0) atomicAdd(&g_sumx, bs);
    bs = blockSum(sy, s); if (threadIdx.x == 0) atomicAdd(&g_sumy, bs);
}

// fused: normalize (needs stats) + scan1 block-partials (needs deg)
__global__ void __launch_bounds__(256) k_norm_scan1(const float* __restrict__ x) {
    __shared__ int s[256];
    int t = threadIdx.x;
    int i = blockIdx.x * 256 + t;
    // scan1 part
    s[t] = (i < N_NODES) ? ((g_deg[i] + 3) & ~3) : 0;
    __syncthreads();
    for (int o = 128; o > 0; o >>= 1) { if (t < o) s[t] += s[t + o]; __syncthreads(); }
    if (t == 0) g_part[blockIdx.x] = s[0];
    // normalize part
    if (i >= N_NODES) return;
    float maxx = o2f(g_maxx), minx = o2f(g_minx);
    float maxy = o2f(g_maxy), miny = o2f(g_miny);
    float maxa = o2f(g_maxa);
    float meanx = g_sumx / (float)N_NODES, meany = g_sumy / (float)N_NODES;
    bool cond = (maxy - miny) > (maxx - minx);
    const float th = (float)(M_PI / 2.0);
    const float c = cosf(th), sn = sinf(th);
    float px = x[i * 3 + 0], py = x[i * 3 + 1], pa = x[i * 3 + 2];
    float cx, cy, mnx, mny, mxx, mxy;
    if (cond) {
        cx = c * px - sn * py;
        cy = sn * px + c * py;
        mnx = c * meanx - sn * meany;
        mny = sn * meanx + c * meany;
        mxx = o2f(g_maxrx);
        mxy = o2f(g_maxry);
    } else {
        cx = px; cy = py; mnx = meanx; mny = meany; mxx = maxx; mxy = maxy;
    }
    float4 o;
    o.x = (cx - mnx) / mxx;
    o.y = (cy - mny) / mxy;
    o.z = pa / maxa;
    o.w = 0.f;
    ((float4*)g_h0)[i] = o;
}

__global__ void __launch_bounds__(512) k_scan2() {
    __shared__ int s[512];
    int t = threadIdx.x;
    int v = (t < NBLK_N) ? g_part[t] : 0;
    s[t] = v; __syncthreads();
    for (int o = 1; o < 512; o <<= 1) {
        int a = (t >= o) ? s[t - o] : 0;
        __syncthreads();
        s[t] += a;
        __syncthreads();
    }
    if (t < NBLK_N) g_part[t] = s[t] - v;
}

__global__ void __launch_bounds__(256) k_scan3() {
    __shared__ int s[256];
    int t = threadIdx.x;
    int i = blockIdx.x * 256 + t;
    int dreal = (i < N_NODES) ? g_deg[i] : 0;
    int v = (dreal + 3) & ~3;
    s[t] = v; __syncthreads();
    for (int o = 1; o < 256; o <<= 1) {
        int a = (t >= o) ? s[t - o] : 0;
        __syncthreads();
        s[t] += a;
        __syncthreads();
    }
    if (i < N_NODES) {
        int ex = g_part[blockIdx.x] + s[t] - v;   // 4-aligned
        g_row[i] = ex;
        g_cur[i] = ex;
        g_invdeg[i] = 1.0f / (float)(dreal > 0 ? dreal : 1);
    }
}

__global__ void k_scatter(const int* __restrict__ src, const int* __restrict__ dst) {
    int e4 = blockIdx.x * blockDim.x + threadIdx.x;
    if (e4 * 4 < N_EDGES) {
        int4 d = ((const int4*)dst)[e4];
        int4 sv = ((const int4*)src)[e4];
        int p0 = atomicAdd(&g_cur[d.x], 1); g_srcs[p0] = sv.x;
        int p1 = atomicAdd(&g_cur[d.y], 1); g_srcs[p1] = sv.y;
        int p2 = atomicAdd(&g_cur[d.z], 1); g_srcs[p2] = sv.z;
        int p3 = atomicAdd(&g_cur[d.w], 1); g_srcs[p3] = sv.w;
    }
}

// ---------------- gather one row's chunk into acc ----------------
template <bool F32G, int TPN, int ELEM>
__device__ __forceinline__ void gacc(const uint4* __restrict__ gsrc, int idx, int q,
                                     float (&acc)[ELEM]) {
    uint4 v = gsrc[(size_t)idx * TPN + q];
    if constexpr (F32G) {
        acc[0] += __uint_as_float(v.x);
        acc[1] += __uint_as_float(v.y);
        acc[2] += __uint_as_float(v.z);
        acc[3] += __uint_as_float(v.w);
    } else {
        float2 f0 = __half22float2(*(const __half2*)&v.x);
        float2 f1 = __half22float2(*(const __half2*)&v.y);
        float2 f2 = __half22float2(*(const __half2*)&v.z);
        float2 f3 = __half22float2(*(const __half2*)&v.w);
        acc[0] += f0.x; acc[1] += f0.y;
        acc[2] += f1.x; acc[3] += f1.y;
        acc[4] += f2.x; acc[5] += f2.y;
        acc[6] += f3.x; acc[7] += f3.y;
    }
}

// ---------------- fused SAGE layer (4-thread node groups: TPN chunks x ES splits) ----
// TPN  = 16B chunks per gather row ; ES = edge-split factor ; TPN*ES == 4
// F32G = gather chunks are 4 fp32 (L1 only) instead of 8 fp16
// FI   = input dim for x@wr ; FIS = fp32 row stride of xin
// FO   = output dim ; RES = residual ; PRE = gather rows already @wl
// GH   = write fp16 copy of out for next layer gather (FO halves/row)
// XFI/XFO = fused phase-3 pre-transform y = out @ xwl -> fp16 (XFI==FO)
// MLPH = fused phase-3 MLP head + softmax (L7 only; writes float2 to mout)
template <int TPN, int ES, bool F32G, int FI, int FIS, int FO, bool RES, bool PRE, bool GH,
          int XFI, int XFO, bool MLPH>
__global__ void __launch_bounds__(256) k_sage(const uint4* __restrict__ gsrc,
                                              const float* __restrict__ xin,
                                              const float* __restrict__ res,
                                              float* __restrict__ xout,
                                              const float* __restrict__ wl,
                                              const float* __restrict__ bl,
                                              const float* __restrict__ wr,
                                              const float* __restrict__ xwl,
                                              __half* __restrict__ ghout,
                                              const float* __restrict__ w1, const float* __restrict__ b1,
                                              const float* __restrict__ w2, const float* __restrict__ b2,
                                              const float* __restrict__ w3, const float* __restrict__ b3,
                                              float* __restrict__ mout) {
    static_assert(TPN * ES == 4, "4-thread node groups");
    constexpr int ELEM = F32G ? 4 : 8;
    constexpr int HD = TPN * ELEM;
    constexpr int NB = 64;              // nodes per block (4 threads each)
    constexpr bool SOUT = (XFO > 0) || MLPH;
    __shared__ __align__(16) float s_mean[NB * HD];
    __shared__ __align__(16) float s_wl[PRE ? 2 : FI * FO];
    __shared__ __align__(16) float s_wr[FI * FO];
    __shared__ float s_bl[FO];
    __shared__ __align__(16) float s_out[SOUT ? NB * FO : 1];
    __shared__ __align__(16) float s_xwl[XFO ? XFI * XFO : 1];
    __shared__ float m_w1[MLPH ? 256 : 1], m_b1[MLPH ? 32 : 1];
    __shared__ float m_w2[MLPH ? 512 : 1], m_b2[MLPH ? 16 : 1];
    __shared__ float m_w3[MLPH ? 32 : 1], m_b3[MLPH ? 2 : 1];
    int t = threadIdx.x;
    if constexpr (!PRE) { for (int i = t; i < FI * FO; i += 256) s_wl[i] = wl[i]; }
    for (int i = t; i < FI * FO; i += 256) s_wr[i] = wr[i];
    if constexpr (XFO > 0) { for (int i = t; i < XFI * XFO; i += 256) s_xwl[i] = xwl[i]; }
    if constexpr (MLPH) {
        if (t < 256) m_w1[t] = w1[t];
        for (int i = t; i < 512; i += 256) m_w2[i] = w2[i];
        if (t < 32) { m_b1[t] = b1[t]; m_w3[t] = w3[t]; }
        if (t < 16) m_b2[t] = b2[t];
        if (t < 2) m_b3[t] = b3[t];
    }
    if (t < FO) s_bl[t] = bl[t];

    int nbase = blockIdx.x * NB;

    // ---- phase 1: mean aggregation; per node: TPN chunk-threads x ES edge-split,
    //      depth-2 quad pipeline ----
    {
        int nl = t >> 2;
        int sub = t & 3;
        int q = sub % TPN;
        int es = sub / TPN;
        int n = nbase + nl;
        float acc[ELEM];
#pragma unroll
        for (int k = 0; k < ELEM; k++) acc[k] = 0.f;
        if (n < N_NODES) {
            int start = g_row[n];                  // 4-aligned
            int dg = g_deg[n];
            const int* sp = g_srcs + start;
            int Q = dg >> 2;
            int nq = (Q > es) ? ((Q - es + ES - 1) / ES) : 0;  // quads for this split
            if (nq > 0) {
                const int4* qp = (const int4*)sp + es;
                int4 c0 = qp[0];
                int4 c1;
                if (nq > 1) c1 = qp[ES];
                for (int i2 = 2; i2 < nq; i2++) {
                    int4 nx = qp[(size_t)i2 * ES];            // prefetch quad i2
                    gacc<F32G, TPN, ELEM>(gsrc, c0.x, q, acc);
                    gacc<F32G, TPN, ELEM>(gsrc, c0.y, q, acc);
                    gacc<F32G, TPN, ELEM>(gsrc, c0.z, q, acc);
                    gacc<F32G, TPN, ELEM>(gsrc, c0.w, q, acc);
                    c0 = c1; c1 = nx;
                }
                gacc<F32G, TPN, ELEM>(gsrc, c0.x, q, acc);
                gacc<F32G, TPN, ELEM>(gsrc, c0.y, q, acc);
                gacc<F32G, TPN, ELEM>(gsrc, c0.z, q, acc);
                gacc<F32G, TPN, ELEM>(gsrc, c0.w, q, acc);
                if (nq > 1) {
                    gacc<F32G, TPN, ELEM>(gsrc, c1.x, q, acc);
                    gacc<F32G, TPN, ELEM>(gsrc, c1.y, q, acc);
                    gacc<F32G, TPN, ELEM>(gsrc, c1.z, q, acc);
                    gacc<F32G, TPN, ELEM>(gsrc, c1.w, q, acc);
                }
            }
            if (es == 0) {
                for (int e = Q * 4; e < dg; e++)
                    gacc<F32G, TPN, ELEM>(gsrc, sp[e], q, acc);
            }
        }
        // reduce across edge-split lanes (stride TPN within the 4-lane group)
#pragma unroll
        for (int off = TPN; off < 4; off <<= 1) {
#pragma unroll
            for (int k = 0; k < ELEM; k++)
                acc[k] += __shfl_xor_sync(0xffffffffu, acc[k], off);
        }
        if (n < N_NODES && es == 0) {
            float inv = g_invdeg[n];
#pragma unroll
            for (int k = 0; k < ELEM; k++)
                s_mean[nl * HD + q * ELEM + k] = acc[k] * inv;
        }
    }
    __syncthreads();

    // ---- phase 2: out = tanh(mean@wl + bl + x@wr) [+res] ----
    constexpr int PAIRS = FO / 2;
    constexpr int NP2 = 256 / PAIRS;
    for (int p = 0; p < NB; p += NP2) {
        int nl2 = p + t / PAIRS;
        int fo2 = t % PAIRS;
        if (nl2 < NB) {
            int n = nbase + nl2;
            if (n < N_NODES) {
                float b0 = s_bl[2 * fo2], b1v = s_bl[2 * fo2 + 1];
                if constexpr (PRE) {
                    b0 += s_mean[nl2 * HD + 2 * fo2];
                    b1v += s_mean[nl2 * HD + 2 * fo2 + 1];
                }
                u64 v = pack2(b0, b1v);
                const float* xr = xin + (size_t)n * FIS;
#pragma unroll
                for (int i = 0; i < FI; i++) {
                    float xi = xr[i];
                    u64 xv = pack2(xi, xi);
                    v = fma2(xv, ((const u64*)s_wr)[i * PAIRS + fo2], v);
                    if constexpr (!PRE) {
                        float mi = s_mean[nl2 * HD + i];
                        u64 mv = pack2(mi, mi);
                        v = fma2(mv, ((const u64*)s_wl)[i * PAIRS + fo2], v);
                    }
                }
                float r0, r1; unpack2(v, r0, r1);
                r0 = tanhf(r0); r1 = tanhf(r1);
                if constexpr (RES) {
                    float2 rr = ((const float2*)res)[(size_t)n * PAIRS + fo2];
                    r0 += rr.x; r1 += rr.y;
                }
                if constexpr (!MLPH) {
                    ((float2*)xout)[(size_t)n * PAIRS + fo2] = make_float2(r0, r1);
                }
                if constexpr (GH) {
                    ((__half2*)ghout)[(size_t)n * PAIRS + fo2] =
                        __float22half2_rn(make_float2(r0, r1));
                }
                if constexpr (SOUT) {
                    s_out[nl2 * FO + 2 * fo2] = r0;
                    s_out[nl2 * FO + 2 * fo2 + 1] = r1;
                }
            }
        }
    }

    // ---- phase 3a: y = out @ xwl -> fp16 gather rows for next layer ----
    if constexpr (XFO > 0) {
        __syncthreads();
        for (int base = 0; base < NB * XFO; base += 256) {
            int idx2 = base + t;
            if (idx2 < NB * XFO) {
                int nl = idx2 / XFO, fo = idx2 % XFO;
                int n = nbase + nl;
                if (n < N_NODES) {
                    float v = 0.f;
#pragma unroll
                    for (int i = 0; i < XFI; i++)
                        v += s_out[nl * XFI + i] * s_xwl[i * XFO + fo];
                    ghout[(size_t)n * XFO + fo] = __float2half_rn(v);
                }
            }
        }
    }

    // ---- phase 3b: fused MLP head + softmax (L7) ----
    if constexpr (MLPH) {
        __syncthreads();
        if (t < NB) {
            int n = nbase + t;
            if (n < N_NODES) {
                float in8[8];
#pragma unroll
                for (int i = 0; i < 8; i++) in8[i] = s_out[t * 8 + i];
                float a[32];
#pragma unroll
                for (int j = 0; j < 32; j++) {
                    float v = m_b1[j];
#pragma unroll
                    for (int i = 0; i < 8; i++) v += in8[i] * m_w1[i * 32 + j];
                    a[j] = tanhf(v);
                }
                float bb[16];
#pragma unroll
                for (int j = 0; j < 16; j++) {
                    float v = m_b2[j];
#pragma unroll
                    for (int i = 0; i < 32; i++) v += a[i] * m_w2[i * 16 + j];
                    bb[j] = tanhf(v);
                }
                float c0 = m_b3[0], c1 = m_b3[1];
#pragma unroll
                for (int i = 0; i < 16; i++) { c0 += bb[i] * m_w3[i * 2 + 0]; c1 += bb[i] * m_w3[i * 2 + 1]; }
                float m = fmaxf(c0, c1);
                float e0 = expf(c0 - m), e1 = expf(c1 - m);
                float inv = 1.f / (e0 + e1);
                ((float2*)mout)[n] = make_float2(e0 * inv, e1 * inv);
            }
        }
    }
}

// ---------------- launch ----------------
extern "C" void kernel_launch(void* const* d_in, const int* in_sizes, int n_in,
                              void* d_out, int out_size) {
    const float* x = (const float*)d_in[0];
    const int* ei = (const int*)d_in[1];
    const int* src = ei;
    const int* dst = ei + N_EDGES;

    const float* cw[7][3];
    for (int l = 0; l < 7; l++) {
        cw[l][0] = (const float*)d_in[2 + 3 * l + 0];
        cw[l][1] = (const float*)d_in[2 + 3 * l + 1];
        cw[l][2] = (const float*)d_in[2 + 3 * l + 2];
    }
    const float* lin1_w = (const float*)d_in[23];
    const float* lin1_b = (const float*)d_in[24];
    const float* lin2_w = (const float*)d_in[25];
    const float* lin2_b = (const float*)d_in[26];
    const float* lin3_w = (const float*)d_in[27];
    const float* lin3_b = (const float*)d_in[28];
    float* out = (float*)d_out;

    float *h0, *x1, *x2, *x3, *x4, *h5, *h6;
    uint4 *bufA, *bufB;
    cudaGetSymbolAddress((void**)&h0, g_h0);
    cudaGetSymbolAddress((void**)&x1, g_x1);
    cudaGetSymbolAddress((void**)&x2, g_x2);
    cudaGetSymbolAddress((void**)&x3, g_x3);
    cudaGetSymbolAddress((void**)&x4, g_x4);
    cudaGetSymbolAddress((void**)&h5, g_h5);
    cudaGetSymbolAddress((void**)&h6, g_h6);
    cudaGetSymbolAddress((void**)&bufA, g_bufA);
    cudaGetSymbolAddress((void**)&bufB, g_bufB);
    __half* hA = (__half*)bufA;
    __half* hB = (__half*)bufB;

    // setup + CSR build (fused)
    k_zero_init<<<NBLK_N, 256>>>();
    k_count_stats<<<NBLK_E4, 256>>>(dst, x);
    k_norm_scan1<<<NBLK_N, 256>>>(x);
    k_scan2<<<1, 512>>>();
    k_scan3<<<NBLK_N, 256>>>();
    k_scatter<<<NBLK_E4, 256>>>(src, dst);

    // L1: 3->8   gather h0 fp32 (TPN=1,ES=4) -> x1 + x1h(B)
    k_sage<1, 4, true, 3, 4, 8, false, false, true, 0, 0, false><<<NBLK_S, 256>>>(
        (const uint4*)h0, h0, nullptr, x1, cw[0][0], cw[0][1], cw[0][2], nullptr, hB,
        nullptr, nullptr, nullptr, nullptr, nullptr, nullptr, nullptr);
    // L2: 8->16  gather x1h(B) (TPN=1,ES=4) -> x2 + x2h(A)
    k_sage<1, 4, false, 8, 8, 16, false, false, true, 0, 0, false><<<NBLK_S, 256>>>(
        bufB, x1, nullptr, x2, cw[1][0], cw[1][1], cw[1][2], nullptr, hA,
        nullptr, nullptr, nullptr, nullptr, nullptr, nullptr, nullptr);
    // L3: 16->32 gather x2h(A) (TPN=2,ES=2) -> x3 + x3h(B)
    k_sage<2, 2, false, 16, 16, 32, false, false, true, 0, 0, false><<<NBLK_S, 256>>>(
        bufA, x2, nullptr, x3, cw[2][0], cw[2][1], cw[2][2], nullptr, hB,
        nullptr, nullptr, nullptr, nullptr, nullptr, nullptr, nullptr);
    // L4: 32->64 gather x3h(B) (TPN=4,ES=1) -> x4 ; phase3 y5 = x4@wl5 (64->32) -> A
    k_sage<4, 1, false, 32, 32, 64, false, false, false, 64, 32, false><<<NBLK_S, 256>>>(
        bufB, x3, nullptr, x4, cw[3][0], cw[3][1], cw[3][2], cw[4][0], hA,
        nullptr, nullptr, nullptr, nullptr, nullptr, nullptr, nullptr);
    // L5: (PRE) gather y5h(A) (TPN=4,ES=1), self x4(64), res x3 -> h5 ; y6 = h5@wl6 -> B
    k_sage<4, 1, false, 64, 64, 32, true, true, false, 32, 16, false><<<NBLK_S, 256>>>(
        bufA, x4, x3, h5, cw[4][0], cw[4][1], cw[4][2], cw[5][0], hB,
        nullptr, nullptr, nullptr, nullptr, nullptr, nullptr, nullptr);
    // L6: (PRE) gather y6h(B) (TPN=2,ES=2), self h5(32), res x2 -> h6 ; y7 = h6@wl7 -> A
    k_sage<2, 2, false, 32, 32, 16, true, true, false, 16, 8, false><<<NBLK_S, 256>>>(
        bufB, h5, x2, h6, cw[5][0], cw[5][1], cw[5][2], cw[6][0], hA,
        nullptr, nullptr, nullptr, nullptr, nullptr, nullptr, nullptr);
    // L7: (PRE) gather y7h(A) (TPN=1,ES=4), self h6(16), res x1 ; fused MLP head -> out
    k_sage<1, 4, false, 16, 16, 8, true, true, false, 0, 0, true><<<NBLK_S, 256>>>(
        bufA, h6, x1, nullptr, cw[6][0], cw[6][1], cw[6][2], nullptr, nullptr,
        lin1_w, lin1_b, lin2_w, lin2_b, lin3_w, lin3_b, out);
}